// round 15
// baseline (speedup 1.0000x reference)
#include <cuda_runtime.h>
#include <math.h>

#define NT 8192
#define CD 128
#define NCLUS 256
#define SQRT_C 11.313708498984761f
#define FLTMAX 3.402823466e38f

// ---------------- scratch (static device globals; no allocs) ----------------
__device__ float g_D2[(long long)NT * NT];   // 256 MB squared-distance matrix
__device__ float g_sq[NT];
__device__ float g_density[NT];
__device__ float g_score[NT];

// ---------------- jax threefry2x32 noise, bit-exact ----------------
__device__ __forceinline__ unsigned int rotl(unsigned int x, int d) {
    return (x << d) | (x >> (32 - d));
}

__device__ float jax_noise(int i) {
    unsigned int x0, x1;
    if (i < 4096) { x0 = (unsigned int)i;          x1 = (unsigned int)(i + 4096); }
    else          { x0 = (unsigned int)(i - 4096); x1 = (unsigned int)i; }
    const unsigned int ks0 = 0u, ks1 = 1u, ks2 = 0u ^ 1u ^ 0x1BD11BDAu;
    x0 += ks0; x1 += ks1;
#define TFR(r) { x0 += x1; x1 = rotl(x1, r); x1 ^= x0; }
    TFR(13) TFR(15) TFR(26) TFR(6)
    x0 += ks1; x1 += ks2 + 1u;
    TFR(17) TFR(29) TFR(16) TFR(24)
    x0 += ks2; x1 += ks0 + 2u;
    TFR(13) TFR(15) TFR(26) TFR(6)
    x0 += ks0; x1 += ks1 + 3u;
    TFR(17) TFR(29) TFR(16) TFR(24)
    x0 += ks1; x1 += ks2 + 4u;
    TFR(13) TFR(15) TFR(26) TFR(6)
    x0 += ks2; x1 += ks0 + 5u;
#undef TFR
    unsigned int bits = (i < 4096) ? x0 : x1;
    unsigned int fb = (bits >> 9) | 0x3f800000u;
    return __uint_as_float(fb) - 1.0f;   // uniform [0,1), exactly jax's mapping
}

// ---------------- kernel 1: row sum-of-squares ----------------
__global__ void k_rownorm(const float* __restrict__ X) {
    int row = blockIdx.x * 8 + (threadIdx.x >> 5);
    int lane = threadIdx.x & 31;
    const float4 v = reinterpret_cast<const float4*>(X)[(long long)row * 32 + lane];
    float s = __fmul_rn(v.x, v.x);
    s = __fadd_rn(s, __fmul_rn(v.y, v.y));
    s = __fadd_rn(s, __fmul_rn(v.z, v.z));
    s = __fadd_rn(s, __fmul_rn(v.w, v.w));
    #pragma unroll
    for (int off = 16; off > 0; off >>= 1)
        s = __fadd_rn(s, __shfl_xor_sync(0xFFFFFFFFu, s, off));
    if (lane == 0) g_sq[row] = s;
}

// ---------------- kernel 2: symmetric SGEMM -> D2 ---------------------------------
// k-step 32 (8 barriers/CTA), conflict-free 4+4 LDS mapping, 2 CTA/SM pinned,
// D2 stores cache-streaming (__stcs).
__global__ void __launch_bounds__(256, 2) k_gemm(const float* __restrict__ X) {
    __shared__ float As[32][128];
    __shared__ float Bs[32][128];

    int rem = blockIdx.x;
    int bi = 0, span = 64;
    while (rem >= span) { rem -= span; span--; bi++; }
    int bj = bi + rem;

    const int rows = bi * 128, cols = bj * 128;
    const int tid = threadIdx.x;
    const int tx = tid & 15, ty = tid >> 4;

    float acc[8][8];
    #pragma unroll
    for (int m = 0; m < 8; m++)
        #pragma unroll
        for (int n = 0; n < 8; n++) acc[m][n] = 0.0f;

    const int lrow = tid >> 1;            // 0..127
    const int lk = (tid & 1) * 16;        // 0 or 16

    for (int k0 = 0; k0 < CD; k0 += 32) {
        const float* pa = X + (long long)(rows + lrow) * CD + k0 + lk;
        const float* pb = X + (long long)(cols + lrow) * CD + k0 + lk;
        float4 va0 = *reinterpret_cast<const float4*>(pa);
        float4 va1 = *reinterpret_cast<const float4*>(pa + 4);
        float4 va2 = *reinterpret_cast<const float4*>(pa + 8);
        float4 va3 = *reinterpret_cast<const float4*>(pa + 12);
        float4 vb0 = *reinterpret_cast<const float4*>(pb);
        float4 vb1 = *reinterpret_cast<const float4*>(pb + 4);
        float4 vb2 = *reinterpret_cast<const float4*>(pb + 8);
        float4 vb3 = *reinterpret_cast<const float4*>(pb + 12);
        __syncthreads();
        As[lk + 0][lrow] = va0.x;  As[lk + 1][lrow] = va0.y;
        As[lk + 2][lrow] = va0.z;  As[lk + 3][lrow] = va0.w;
        As[lk + 4][lrow] = va1.x;  As[lk + 5][lrow] = va1.y;
        As[lk + 6][lrow] = va1.z;  As[lk + 7][lrow] = va1.w;
        As[lk + 8][lrow] = va2.x;  As[lk + 9][lrow] = va2.y;
        As[lk + 10][lrow] = va2.z; As[lk + 11][lrow] = va2.w;
        As[lk + 12][lrow] = va3.x; As[lk + 13][lrow] = va3.y;
        As[lk + 14][lrow] = va3.z; As[lk + 15][lrow] = va3.w;
        Bs[lk + 0][lrow] = vb0.x;  Bs[lk + 1][lrow] = vb0.y;
        Bs[lk + 2][lrow] = vb0.z;  Bs[lk + 3][lrow] = vb0.w;
        Bs[lk + 4][lrow] = vb1.x;  Bs[lk + 5][lrow] = vb1.y;
        Bs[lk + 6][lrow] = vb1.z;  Bs[lk + 7][lrow] = vb1.w;
        Bs[lk + 8][lrow] = vb2.x;  Bs[lk + 9][lrow] = vb2.y;
        Bs[lk + 10][lrow] = vb2.z; Bs[lk + 11][lrow] = vb2.w;
        Bs[lk + 12][lrow] = vb3.x; Bs[lk + 13][lrow] = vb3.y;
        Bs[lk + 14][lrow] = vb3.z; Bs[lk + 15][lrow] = vb3.w;
        __syncthreads();

        #pragma unroll 16
        for (int kk = 0; kk < 32; kk++) {
            float4 a0 = *reinterpret_cast<float4*>(&As[kk][ty * 4]);        // rows blk0
            float4 a1 = *reinterpret_cast<float4*>(&As[kk][64 + ty * 4]);   // rows blk1
            float4 b0 = *reinterpret_cast<float4*>(&Bs[kk][tx * 4]);        // cols blk0
            float4 b1 = *reinterpret_cast<float4*>(&Bs[kk][64 + tx * 4]);   // cols blk1
            float am[8] = {a0.x, a0.y, a0.z, a0.w, a1.x, a1.y, a1.z, a1.w};
            float bn[8] = {b0.x, b0.y, b0.z, b0.w, b1.x, b1.y, b1.z, b1.w};
            #pragma unroll
            for (int m = 0; m < 8; m++)
                #pragma unroll
                for (int n = 0; n < 8; n++)
                    acc[m][n] = __fmaf_rn(am[m], bn[n], acc[m][n]);
        }
    }

    float sr[8], sc[8];
    #pragma unroll
    for (int m = 0; m < 8; m++)
        sr[m] = g_sq[rows + (m >> 2) * 64 + ty * 4 + (m & 3)];
    #pragma unroll
    for (int n = 0; n < 8; n++)
        sc[n] = g_sq[cols + (n >> 2) * 64 + tx * 4 + (n & 3)];

    float v[8][8];
    #pragma unroll
    for (int m = 0; m < 8; m++)
        #pragma unroll
        for (int n = 0; n < 8; n++)
            v[m][n] = __fadd_rn(__fadd_rn(sr[m], sc[n]), -2.0f * acc[m][n]);

    #pragma unroll
    for (int m = 0; m < 8; m++) {
        const int gr = rows + (m >> 2) * 64 + ty * 4 + (m & 3);
        long long base = (long long)gr * NT + cols;
        __stcs(reinterpret_cast<float4*>(g_D2 + base + tx * 4),
               make_float4(v[m][0], v[m][1], v[m][2], v[m][3]));
        __stcs(reinterpret_cast<float4*>(g_D2 + base + 64 + tx * 4),
               make_float4(v[m][4], v[m][5], v[m][6], v[m][7]));
    }
    if (bi != bj) {
        #pragma unroll
        for (int n = 0; n < 8; n++) {
            const int gc = cols + (n >> 2) * 64 + tx * 4 + (n & 3);
            long long base = (long long)gc * NT + rows;
            __stcs(reinterpret_cast<float4*>(g_D2 + base + ty * 4),
                   make_float4(v[0][n], v[1][n], v[2][n], v[3][n]));
            __stcs(reinterpret_cast<float4*>(g_D2 + base + 64 + ty * 4),
                   make_float4(v[4][n], v[5][n], v[6][n], v[7][n]));
        }
    }
}

// ---------------- kernel 3 (pass A): 5-NN density (MLP-8 streaming) ---------------
__global__ void __launch_bounds__(256) k_knn() {
    const int i = blockIdx.x;
    const int t = threadIdx.x;
    const float4* __restrict__ row4 =
        reinterpret_cast<const float4*>(g_D2 + (long long)i * NT);

    float s0 = FLTMAX, s1 = FLTMAX, s2 = FLTMAX, s3 = FLTMAX, s4 = FLTMAX;

    #define INSERT(x)                                                        \
        if (x < s4) {                                                        \
            if (x < s3) { s4 = s3;                                           \
                if (x < s2) { s3 = s2;                                       \
                    if (x < s1) { s2 = s1;                                   \
                        if (x < s0) { s1 = s0; s0 = x; } else s1 = x;        \
                    } else s2 = x;                                           \
                } else s3 = x;                                               \
            } else s4 = x;                                                   \
        }
    #define TRY4(rr)                                                         \
        {                                                                    \
            float mn = fminf(fminf(rr.x, rr.y), fminf(rr.z, rr.w));          \
            if (mn < s4) { INSERT(rr.x) INSERT(rr.y) INSERT(rr.z) INSERT(rr.w) } \
        }

    {   // all 8 loads front-batched (MLP-8), streaming (read-once data)
        float4 r0 = __ldcs(&row4[t]);
        float4 r1 = __ldcs(&row4[t + 256]);
        float4 r2 = __ldcs(&row4[t + 512]);
        float4 r3 = __ldcs(&row4[t + 768]);
        float4 r4 = __ldcs(&row4[t + 1024]);
        float4 r5 = __ldcs(&row4[t + 1280]);
        float4 r6 = __ldcs(&row4[t + 1536]);
        float4 r7 = __ldcs(&row4[t + 1792]);
        TRY4(r0) TRY4(r1) TRY4(r2) TRY4(r3)
        TRY4(r4) TRY4(r5) TRY4(r6) TRY4(r7)
    }
    #undef TRY4
    #undef INSERT

    __shared__ float sh[256 * 5];
    sh[t * 5 + 0] = s0; sh[t * 5 + 1] = s1; sh[t * 5 + 2] = s2;
    sh[t * 5 + 3] = s3; sh[t * 5 + 4] = s4;
    __syncthreads();

    for (int stride = 128; stride >= 1; stride >>= 1) {
        if (t < stride) {
            float* A = &sh[t * 5];
            float* B = &sh[(t + stride) * 5];
            float o[5];
            int ia = 0, ib = 0;
            #pragma unroll
            for (int q = 0; q < 5; q++) {
                float av = (ia < 5) ? A[ia] : FLTMAX;
                float bv = (ib < 5) ? B[ib] : FLTMAX;
                if (av <= bv) { o[q] = av; ia++; } else { o[q] = bv; ib++; }
            }
            #pragma unroll
            for (int q = 0; q < 5; q++) A[q] = o[q];
        }
        __syncthreads();
    }

    if (t == 0) {
        float accv = 0.0f;
        #pragma unroll
        for (int q = 0; q < 5; q++) {
            float d = __fdiv_rn(__fsqrt_rn(fmaxf(sh[q], 0.0f)), SQRT_C);
            accv = __fadd_rn(accv, __fmul_rn(d, d));
        }
        float mean = __fdiv_rn(accv, 5.0f);
        float dens = (float)exp(-(double)mean);
        dens = __fadd_rn(dens, __fmul_rn(jax_noise(i), 1e-6f));
        g_density[i] = dens;
    }
}

// ---------------- kernel 4 (pass B): dist_parent + score (MLP-8 streaming) --------
__global__ void __launch_bounds__(256) k_parent() {
    const int i = blockIdx.x;
    const int t = threadIdx.x;
    const float di = g_density[i];
    const float4* __restrict__ row4 =
        reinterpret_cast<const float4*>(g_D2 + (long long)i * NT);
    const float4* __restrict__ den4 =
        reinterpret_cast<const float4*>(g_density);

    float l0 = FLTMAX, l1 = FLTMAX, l2 = FLTMAX, l3 = FLTMAX;
    #define ACC4(rr, dd)                                   \
        l0 = fminf(l0, (dd.x > di) ? rr.x : FLTMAX);       \
        l1 = fminf(l1, (dd.y > di) ? rr.y : FLTMAX);       \
        l2 = fminf(l2, (dd.z > di) ? rr.z : FLTMAX);       \
        l3 = fminf(l3, (dd.w > di) ? rr.w : FLTMAX);

    {   // all 8 row loads front-batched (MLP-8), streaming; density L2-cached
        float4 r0 = __ldcs(&row4[t]);
        float4 r1 = __ldcs(&row4[t + 256]);
        float4 r2 = __ldcs(&row4[t + 512]);
        float4 r3 = __ldcs(&row4[t + 768]);
        float4 r4 = __ldcs(&row4[t + 1024]);
        float4 r5 = __ldcs(&row4[t + 1280]);
        float4 r6 = __ldcs(&row4[t + 1536]);
        float4 r7 = __ldcs(&row4[t + 1792]);
        float4 d0 = den4[t];
        float4 d1 = den4[t + 256];
        float4 d2 = den4[t + 512];
        float4 d3 = den4[t + 768];
        float4 d4 = den4[t + 1024];
        float4 d5 = den4[t + 1280];
        float4 d6 = den4[t + 1536];
        float4 d7 = den4[t + 1792];
        ACC4(r0, d0) ACC4(r1, d1) ACC4(r2, d2) ACC4(r3, d3)
        ACC4(r4, d4) ACC4(r5, d5) ACC4(r6, d6) ACC4(r7, d7)
    }
    #undef ACC4
    float lmin = fminf(fminf(l0, l1), fminf(l2, l3));

    __shared__ float sm[256];
    sm[t] = lmin;
    __syncthreads();
    for (int stride = 128; stride >= 1; stride >>= 1) {
        if (t < stride) sm[t] = fminf(sm[t], sm[t + stride]);
        __syncthreads();
    }

    if (t == 0) {
        float m = sm[0];
        if (m >= FLTMAX) {
            g_score[i] = FLTMAX;   // density argmax: strict top-1 either way
        } else {
            float dp = __fdiv_rn(__fsqrt_rn(fmaxf(m, 0.0f)), SQRT_C);
            g_score[i] = __fmul_rn(dp, di);
        }
    }
}

// ---------------- kernel 5: exact top-256 (descending, lower-index-first ties) ----
__global__ void k_topk(float* __restrict__ out) {
    extern __shared__ char dyn[];
    float* ss = reinterpret_cast<float*>(dyn);                            // 32KB
    unsigned short* si = reinterpret_cast<unsigned short*>(dyn + NT * 4); // 16KB
    const int t = threadIdx.x;  // 1024 threads

    for (int i = t; i < NT; i += 1024) {
        ss[i] = g_score[i];
        si[i] = (unsigned short)i;
    }
    __syncthreads();

    for (int k = 2; k <= NT; k <<= 1) {
        for (int j = k >> 1; j > 0; j >>= 1) {
            for (int i = t; i < NT; i += 1024) {
                int ixj = i ^ j;
                if (ixj > i) {
                    unsigned short ia = si[i], ib = si[ixj];
                    unsigned long long ka =
                        ((unsigned long long)__float_as_uint(ss[ia]) << 32) |
                        (unsigned int)(NT - 1 - (int)ia);
                    unsigned long long kb =
                        ((unsigned long long)__float_as_uint(ss[ib]) << 32) |
                        (unsigned int)(NT - 1 - (int)ib);
                    bool desc = ((i & k) == 0);
                    if (desc ? (ka < kb) : (ka > kb)) { si[i] = ib; si[ixj] = ia; }
                }
            }
            __syncthreads();
        }
    }

    if (t < NCLUS) out[t] = (float)si[t];   // indices as float32
}

// ---------------- launch ----------------
extern "C" void kernel_launch(void* const* d_in, const int* in_sizes, int n_in,
                              void* d_out, int out_size) {
    const float* X = (const float*)d_in[0];
    float* out = (float*)d_out;

    k_rownorm<<<NT / 8, 256>>>(X);
    k_gemm<<<(64 * 65) / 2, 256>>>(X);
    k_knn<<<NT, 256>>>();
    k_parent<<<NT, 256>>>();
    k_topk<<<1, 1024, 48 * 1024>>>(out);
}

// round 16
// speedup vs baseline: 1.0273x; 1.0273x over previous
#include <cuda_runtime.h>
#include <math.h>

#define NT 8192
#define CD 128
#define NCLUS 256
#define SQRT_C 11.313708498984761f
#define FLTMAX 3.402823466e38f

// ---------------- scratch (static device globals; no allocs) ----------------
__device__ float g_D2[(long long)NT * NT];   // 256 MB squared-distance matrix
__device__ float g_sq[NT];
__device__ float g_density[NT];
__device__ float g_score[NT];

// ---------------- jax threefry2x32 noise, bit-exact ----------------
__device__ __forceinline__ unsigned int rotl(unsigned int x, int d) {
    return (x << d) | (x >> (32 - d));
}

__device__ float jax_noise(int i) {
    unsigned int x0, x1;
    if (i < 4096) { x0 = (unsigned int)i;          x1 = (unsigned int)(i + 4096); }
    else          { x0 = (unsigned int)(i - 4096); x1 = (unsigned int)i; }
    const unsigned int ks0 = 0u, ks1 = 1u, ks2 = 0u ^ 1u ^ 0x1BD11BDAu;
    x0 += ks0; x1 += ks1;
#define TFR(r) { x0 += x1; x1 = rotl(x1, r); x1 ^= x0; }
    TFR(13) TFR(15) TFR(26) TFR(6)
    x0 += ks1; x1 += ks2 + 1u;
    TFR(17) TFR(29) TFR(16) TFR(24)
    x0 += ks2; x1 += ks0 + 2u;
    TFR(13) TFR(15) TFR(26) TFR(6)
    x0 += ks0; x1 += ks1 + 3u;
    TFR(17) TFR(29) TFR(16) TFR(24)
    x0 += ks1; x1 += ks2 + 4u;
    TFR(13) TFR(15) TFR(26) TFR(6)
    x0 += ks2; x1 += ks0 + 5u;
#undef TFR
    unsigned int bits = (i < 4096) ? x0 : x1;
    unsigned int fb = (bits >> 9) | 0x3f800000u;
    return __uint_as_float(fb) - 1.0f;   // uniform [0,1), exactly jax's mapping
}

// ---------------- kernel 1: row sum-of-squares ----------------
__global__ void k_rownorm(const float* __restrict__ X) {
    int row = blockIdx.x * 8 + (threadIdx.x >> 5);
    int lane = threadIdx.x & 31;
    const float4 v = reinterpret_cast<const float4*>(X)[(long long)row * 32 + lane];
    float s = __fmul_rn(v.x, v.x);
    s = __fadd_rn(s, __fmul_rn(v.y, v.y));
    s = __fadd_rn(s, __fmul_rn(v.z, v.z));
    s = __fadd_rn(s, __fmul_rn(v.w, v.w));
    #pragma unroll
    for (int off = 16; off > 0; off >>= 1)
        s = __fadd_rn(s, __shfl_xor_sync(0xFFFFFFFFu, s, off));
    if (lane == 0) g_sq[row] = s;
}

// ---------------- kernel 2: symmetric SGEMM -> D2 ---------------------------------
// k-step 32, conflict-free 4+4 LDS mapping, 2 CTA/SM pinned, __stcs stores.
// Mirror stores go through a SMEM transpose (pool reuse) -> fully coalesced.
// Diagonal tiles are ordered LAST so the tail wave is the cheap tiles.
#define AS(k, r) pool[(k) * 128 + (r)]
#define BS(k, r) pool[4096 + (k) * 128 + (r)]

__global__ void __launch_bounds__(256, 2) k_gemm(const float* __restrict__ X) {
    __shared__ float pool[8192];   // As | Bs during mainloop; transpose buf in epilogue

    // tile decode: 2016 non-diagonal pairs (bi<bj) first, 64 diagonals last
    int bi, bj;
    if (blockIdx.x < 2016) {
        int rem = blockIdx.x;
        bi = 0;
        int span = 63;
        while (rem >= span) { rem -= span; span--; bi++; }
        bj = bi + 1 + rem;
    } else {
        bi = bj = blockIdx.x - 2016;
    }
    const bool diag = (bi == bj);

    const int rows = bi * 128, cols = bj * 128;
    const int tid = threadIdx.x;
    const int tx = tid & 15, ty = tid >> 4;

    float acc[8][8];
    #pragma unroll
    for (int m = 0; m < 8; m++)
        #pragma unroll
        for (int n = 0; n < 8; n++) acc[m][n] = 0.0f;

    const int lrow = tid >> 1;            // 0..127
    const int lk = (tid & 1) * 16;        // 0 or 16

    for (int k0 = 0; k0 < CD; k0 += 32) {
        const float* pa = X + (long long)(rows + lrow) * CD + k0 + lk;
        const float* pb = X + (long long)(cols + lrow) * CD + k0 + lk;
        float4 va0 = *reinterpret_cast<const float4*>(pa);
        float4 va1 = *reinterpret_cast<const float4*>(pa + 4);
        float4 va2 = *reinterpret_cast<const float4*>(pa + 8);
        float4 va3 = *reinterpret_cast<const float4*>(pa + 12);
        float4 vb0 = *reinterpret_cast<const float4*>(pb);
        float4 vb1 = *reinterpret_cast<const float4*>(pb + 4);
        float4 vb2 = *reinterpret_cast<const float4*>(pb + 8);
        float4 vb3 = *reinterpret_cast<const float4*>(pb + 12);
        __syncthreads();
        AS(lk + 0, lrow) = va0.x;  AS(lk + 1, lrow) = va0.y;
        AS(lk + 2, lrow) = va0.z;  AS(lk + 3, lrow) = va0.w;
        AS(lk + 4, lrow) = va1.x;  AS(lk + 5, lrow) = va1.y;
        AS(lk + 6, lrow) = va1.z;  AS(lk + 7, lrow) = va1.w;
        AS(lk + 8, lrow) = va2.x;  AS(lk + 9, lrow) = va2.y;
        AS(lk + 10, lrow) = va2.z; AS(lk + 11, lrow) = va2.w;
        AS(lk + 12, lrow) = va3.x; AS(lk + 13, lrow) = va3.y;
        AS(lk + 14, lrow) = va3.z; AS(lk + 15, lrow) = va3.w;
        BS(lk + 0, lrow) = vb0.x;  BS(lk + 1, lrow) = vb0.y;
        BS(lk + 2, lrow) = vb0.z;  BS(lk + 3, lrow) = vb0.w;
        BS(lk + 4, lrow) = vb1.x;  BS(lk + 5, lrow) = vb1.y;
        BS(lk + 6, lrow) = vb1.z;  BS(lk + 7, lrow) = vb1.w;
        BS(lk + 8, lrow) = vb2.x;  BS(lk + 9, lrow) = vb2.y;
        BS(lk + 10, lrow) = vb2.z; BS(lk + 11, lrow) = vb2.w;
        BS(lk + 12, lrow) = vb3.x; BS(lk + 13, lrow) = vb3.y;
        BS(lk + 14, lrow) = vb3.z; BS(lk + 15, lrow) = vb3.w;
        __syncthreads();

        #pragma unroll 16
        for (int kk = 0; kk < 32; kk++) {
            float4 a0 = *reinterpret_cast<float4*>(&AS(kk, ty * 4));        // rows blk0
            float4 a1 = *reinterpret_cast<float4*>(&AS(kk, 64 + ty * 4));   // rows blk1
            float4 b0 = *reinterpret_cast<float4*>(&BS(kk, tx * 4));        // cols blk0
            float4 b1 = *reinterpret_cast<float4*>(&BS(kk, 64 + tx * 4));   // cols blk1
            float am[8] = {a0.x, a0.y, a0.z, a0.w, a1.x, a1.y, a1.z, a1.w};
            float bn[8] = {b0.x, b0.y, b0.z, b0.w, b1.x, b1.y, b1.z, b1.w};
            #pragma unroll
            for (int m = 0; m < 8; m++)
                #pragma unroll
                for (int n = 0; n < 8; n++)
                    acc[m][n] = __fmaf_rn(am[m], bn[n], acc[m][n]);
        }
    }

    float sr[8], sc[8];
    #pragma unroll
    for (int m = 0; m < 8; m++)
        sr[m] = g_sq[rows + (m >> 2) * 64 + ty * 4 + (m & 3)];
    #pragma unroll
    for (int n = 0; n < 8; n++)
        sc[n] = g_sq[cols + (n >> 2) * 64 + tx * 4 + (n & 3)];

    float v[8][8];
    #pragma unroll
    for (int m = 0; m < 8; m++)
        #pragma unroll
        for (int n = 0; n < 8; n++)
            v[m][n] = __fadd_rn(__fadd_rn(sr[m], sc[n]), -2.0f * acc[m][n]);

    // row-major stores (coalesced, streaming)
    #pragma unroll
    for (int m = 0; m < 8; m++) {
        const int gr = rows + (m >> 2) * 64 + ty * 4 + (m & 3);
        long long base = (long long)gr * NT + cols;
        __stcs(reinterpret_cast<float4*>(g_D2 + base + tx * 4),
               make_float4(v[m][0], v[m][1], v[m][2], v[m][3]));
        __stcs(reinterpret_cast<float4*>(g_D2 + base + 64 + tx * 4),
               make_float4(v[m][4], v[m][5], v[m][6], v[m][7]));
    }

    // mirror stores via SMEM transpose -> coalesced 512B/warp STG
    if (!diag) {
        const int wid = tid >> 5, lane = tid & 31;
        #pragma unroll
        for (int c = 0; c < 4; c++) {          // 4 chunks of 32 mirror rows
            __syncthreads();                    // pool free / prev chunk consumed
            if ((tx >> 3) == (c & 1)) {
                const int nbase = (c >> 1) * 4;
                #pragma unroll
                for (int q = 0; q < 4; q++) {
                    const int n = nbase + q;
                    const int gcl = (tx & 7) * 4 + q;     // local col 0..31
                    *reinterpret_cast<float4*>(&pool[gcl * 132 + ty * 4]) =
                        make_float4(v[0][n], v[1][n], v[2][n], v[3][n]);
                    *reinterpret_cast<float4*>(&pool[gcl * 132 + 64 + ty * 4]) =
                        make_float4(v[4][n], v[5][n], v[6][n], v[7][n]);
                }
            }
            __syncthreads();
            #pragma unroll
            for (int q = 0; q < 4; q++) {       // warp wid -> 4 cols, coalesced rows
                const int gcl = wid * 4 + q;
                const int gc = cols + c * 32 + gcl;
                float4 val = *reinterpret_cast<float4*>(&pool[gcl * 132 + lane * 4]);
                __stcs(reinterpret_cast<float4*>(
                           g_D2 + (long long)gc * NT + rows + lane * 4), val);
            }
        }
    }
}

// ---------------- kernel 3 (pass A): 5-NN density (MLP-8 streaming) ---------------
__global__ void __launch_bounds__(256) k_knn() {
    const int i = blockIdx.x;
    const int t = threadIdx.x;
    const float4* __restrict__ row4 =
        reinterpret_cast<const float4*>(g_D2 + (long long)i * NT);

    float s0 = FLTMAX, s1 = FLTMAX, s2 = FLTMAX, s3 = FLTMAX, s4 = FLTMAX;

    #define INSERT(x)                                                        \
        if (x < s4) {                                                        \
            if (x < s3) { s4 = s3;                                           \
                if (x < s2) { s3 = s2;                                       \
                    if (x < s1) { s2 = s1;                                   \
                        if (x < s0) { s1 = s0; s0 = x; } else s1 = x;        \
                    } else s2 = x;                                           \
                } else s3 = x;                                               \
            } else s4 = x;                                                   \
        }
    #define TRY4(rr)                                                         \
        {                                                                    \
            float mn = fminf(fminf(rr.x, rr.y), fminf(rr.z, rr.w));          \
            if (mn < s4) { INSERT(rr.x) INSERT(rr.y) INSERT(rr.z) INSERT(rr.w) } \
        }

    {   // all 8 loads front-batched (MLP-8), streaming (read-once data)
        float4 r0 = __ldcs(&row4[t]);
        float4 r1 = __ldcs(&row4[t + 256]);
        float4 r2 = __ldcs(&row4[t + 512]);
        float4 r3 = __ldcs(&row4[t + 768]);
        float4 r4 = __ldcs(&row4[t + 1024]);
        float4 r5 = __ldcs(&row4[t + 1280]);
        float4 r6 = __ldcs(&row4[t + 1536]);
        float4 r7 = __ldcs(&row4[t + 1792]);
        TRY4(r0) TRY4(r1) TRY4(r2) TRY4(r3)
        TRY4(r4) TRY4(r5) TRY4(r6) TRY4(r7)
    }
    #undef TRY4
    #undef INSERT

    __shared__ float sh[256 * 5];
    sh[t * 5 + 0] = s0; sh[t * 5 + 1] = s1; sh[t * 5 + 2] = s2;
    sh[t * 5 + 3] = s3; sh[t * 5 + 4] = s4;
    __syncthreads();

    for (int stride = 128; stride >= 1; stride >>= 1) {
        if (t < stride) {
            float* A = &sh[t * 5];
            float* B = &sh[(t + stride) * 5];
            float o[5];
            int ia = 0, ib = 0;
            #pragma unroll
            for (int q = 0; q < 5; q++) {
                float av = (ia < 5) ? A[ia] : FLTMAX;
                float bv = (ib < 5) ? B[ib] : FLTMAX;
                if (av <= bv) { o[q] = av; ia++; } else { o[q] = bv; ib++; }
            }
            #pragma unroll
            for (int q = 0; q < 5; q++) A[q] = o[q];
        }
        __syncthreads();
    }

    if (t == 0) {
        float accv = 0.0f;
        #pragma unroll
        for (int q = 0; q < 5; q++) {
            float d = __fdiv_rn(__fsqrt_rn(fmaxf(sh[q], 0.0f)), SQRT_C);
            accv = __fadd_rn(accv, __fmul_rn(d, d));
        }
        float mean = __fdiv_rn(accv, 5.0f);
        float dens = (float)exp(-(double)mean);
        dens = __fadd_rn(dens, __fmul_rn(jax_noise(i), 1e-6f));
        g_density[i] = dens;
    }
}

// ---------------- kernel 4 (pass B): dist_parent + score (MLP-8 streaming) --------
__global__ void __launch_bounds__(256) k_parent() {
    const int i = blockIdx.x;
    const int t = threadIdx.x;
    const float di = g_density[i];
    const float4* __restrict__ row4 =
        reinterpret_cast<const float4*>(g_D2 + (long long)i * NT);
    const float4* __restrict__ den4 =
        reinterpret_cast<const float4*>(g_density);

    float l0 = FLTMAX, l1 = FLTMAX, l2 = FLTMAX, l3 = FLTMAX;
    #define ACC4(rr, dd)                                   \
        l0 = fminf(l0, (dd.x > di) ? rr.x : FLTMAX);       \
        l1 = fminf(l1, (dd.y > di) ? rr.y : FLTMAX);       \
        l2 = fminf(l2, (dd.z > di) ? rr.z : FLTMAX);       \
        l3 = fminf(l3, (dd.w > di) ? rr.w : FLTMAX);

    {   // all 8 row loads front-batched (MLP-8), streaming; density L2-cached
        float4 r0 = __ldcs(&row4[t]);
        float4 r1 = __ldcs(&row4[t + 256]);
        float4 r2 = __ldcs(&row4[t + 512]);
        float4 r3 = __ldcs(&row4[t + 768]);
        float4 r4 = __ldcs(&row4[t + 1024]);
        float4 r5 = __ldcs(&row4[t + 1280]);
        float4 r6 = __ldcs(&row4[t + 1536]);
        float4 r7 = __ldcs(&row4[t + 1792]);
        float4 d0 = den4[t];
        float4 d1 = den4[t + 256];
        float4 d2 = den4[t + 512];
        float4 d3 = den4[t + 768];
        float4 d4 = den4[t + 1024];
        float4 d5 = den4[t + 1280];
        float4 d6 = den4[t + 1536];
        float4 d7 = den4[t + 1792];
        ACC4(r0, d0) ACC4(r1, d1) ACC4(r2, d2) ACC4(r3, d3)
        ACC4(r4, d4) ACC4(r5, d5) ACC4(r6, d6) ACC4(r7, d7)
    }
    #undef ACC4
    float lmin = fminf(fminf(l0, l1), fminf(l2, l3));

    __shared__ float sm[256];
    sm[t] = lmin;
    __syncthreads();
    for (int stride = 128; stride >= 1; stride >>= 1) {
        if (t < stride) sm[t] = fminf(sm[t], sm[t + stride]);
        __syncthreads();
    }

    if (t == 0) {
        float m = sm[0];
        if (m >= FLTMAX) {
            g_score[i] = FLTMAX;   // density argmax: strict top-1 either way
        } else {
            float dp = __fdiv_rn(__fsqrt_rn(fmaxf(m, 0.0f)), SQRT_C);
            g_score[i] = __fmul_rn(dp, di);
        }
    }
}

// ---------------- kernel 5: exact top-256 (descending, lower-index-first ties) ----
__global__ void k_topk(float* __restrict__ out) {
    extern __shared__ char dyn[];
    float* ss = reinterpret_cast<float*>(dyn);                            // 32KB
    unsigned short* si = reinterpret_cast<unsigned short*>(dyn + NT * 4); // 16KB
    const int t = threadIdx.x;  // 1024 threads

    for (int i = t; i < NT; i += 1024) {
        ss[i] = g_score[i];
        si[i] = (unsigned short)i;
    }
    __syncthreads();

    for (int k = 2; k <= NT; k <<= 1) {
        for (int j = k >> 1; j > 0; j >>= 1) {
            for (int i = t; i < NT; i += 1024) {
                int ixj = i ^ j;
                if (ixj > i) {
                    unsigned short ia = si[i], ib = si[ixj];
                    unsigned long long ka =
                        ((unsigned long long)__float_as_uint(ss[ia]) << 32) |
                        (unsigned int)(NT - 1 - (int)ia);
                    unsigned long long kb =
                        ((unsigned long long)__float_as_uint(ss[ib]) << 32) |
                        (unsigned int)(NT - 1 - (int)ib);
                    bool desc = ((i & k) == 0);
                    if (desc ? (ka < kb) : (ka > kb)) { si[i] = ib; si[ixj] = ia; }
                }
            }
            __syncthreads();
        }
    }

    if (t < NCLUS) out[t] = (float)si[t];   // indices as float32
}

// ---------------- launch ----------------
extern "C" void kernel_launch(void* const* d_in, const int* in_sizes, int n_in,
                              void* d_out, int out_size) {
    const float* X = (const float*)d_in[0];
    float* out = (float*)d_out;

    k_rownorm<<<NT / 8, 256>>>(X);
    k_gemm<<<(64 * 65) / 2, 256>>>(X);
    k_knn<<<NT, 256>>>();
    k_parent<<<NT, 256>>>();
    k_topk<<<1, 1024, 48 * 1024>>>(out);
}

// round 17
// speedup vs baseline: 1.2919x; 1.2576x over previous
#include <cuda_runtime.h>
#include <math.h>

#define NT 8192
#define CD 128
#define NCLUS 256
#define SQRT_C 11.313708498984761f
#define FLTMAX 3.402823466e38f

// ---------------- scratch (static device globals; no allocs) ----------------
__device__ float g_D2[(long long)NT * NT];   // 256 MB squared-distance matrix
__device__ float g_sq[NT];
__device__ float g_density[NT];
__device__ float g_score[NT];

// ---------------- jax threefry2x32 noise, bit-exact ----------------
__device__ __forceinline__ unsigned int rotl(unsigned int x, int d) {
    return (x << d) | (x >> (32 - d));
}

__device__ float jax_noise(int i) {
    unsigned int x0, x1;
    if (i < 4096) { x0 = (unsigned int)i;          x1 = (unsigned int)(i + 4096); }
    else          { x0 = (unsigned int)(i - 4096); x1 = (unsigned int)i; }
    const unsigned int ks0 = 0u, ks1 = 1u, ks2 = 0u ^ 1u ^ 0x1BD11BDAu;
    x0 += ks0; x1 += ks1;
#define TFR(r) { x0 += x1; x1 = rotl(x1, r); x1 ^= x0; }
    TFR(13) TFR(15) TFR(26) TFR(6)
    x0 += ks1; x1 += ks2 + 1u;
    TFR(17) TFR(29) TFR(16) TFR(24)
    x0 += ks2; x1 += ks0 + 2u;
    TFR(13) TFR(15) TFR(26) TFR(6)
    x0 += ks0; x1 += ks1 + 3u;
    TFR(17) TFR(29) TFR(16) TFR(24)
    x0 += ks1; x1 += ks2 + 4u;
    TFR(13) TFR(15) TFR(26) TFR(6)
    x0 += ks2; x1 += ks0 + 5u;
#undef TFR
    unsigned int bits = (i < 4096) ? x0 : x1;
    unsigned int fb = (bits >> 9) | 0x3f800000u;
    return __uint_as_float(fb) - 1.0f;   // uniform [0,1), exactly jax's mapping
}

// ---------------- kernel 1: row sum-of-squares ----------------
__global__ void k_rownorm(const float* __restrict__ X) {
    int row = blockIdx.x * 8 + (threadIdx.x >> 5);
    int lane = threadIdx.x & 31;
    const float4 v = reinterpret_cast<const float4*>(X)[(long long)row * 32 + lane];
    float s = __fmul_rn(v.x, v.x);
    s = __fadd_rn(s, __fmul_rn(v.y, v.y));
    s = __fadd_rn(s, __fmul_rn(v.z, v.z));
    s = __fadd_rn(s, __fmul_rn(v.w, v.w));
    #pragma unroll
    for (int off = 16; off > 0; off >>= 1)
        s = __fadd_rn(s, __shfl_xor_sync(0xFFFFFFFFu, s, off));
    if (lane == 0) g_sq[row] = s;
}

// ---------------- kernel 2: symmetric SGEMM -> D2 ---------------------------------
#define AS(k, r) pool[(k) * 128 + (r)]
#define BS(k, r) pool[4096 + (k) * 128 + (r)]

__global__ void __launch_bounds__(256, 2) k_gemm(const float* __restrict__ X) {
    __shared__ float pool[8192];   // As | Bs mainloop; transpose buf in epilogue

    int bi, bj;
    if (blockIdx.x < 2016) {
        int rem = blockIdx.x;
        bi = 0;
        int span = 63;
        while (rem >= span) { rem -= span; span--; bi++; }
        bj = bi + 1 + rem;
    } else {
        bi = bj = blockIdx.x - 2016;
    }
    const bool diag = (bi == bj);

    const int rows = bi * 128, cols = bj * 128;
    const int tid = threadIdx.x;
    const int tx = tid & 15, ty = tid >> 4;

    float acc[8][8];
    #pragma unroll
    for (int m = 0; m < 8; m++)
        #pragma unroll
        for (int n = 0; n < 8; n++) acc[m][n] = 0.0f;

    const int lrow = tid >> 1;
    const int lk = (tid & 1) * 16;

    for (int k0 = 0; k0 < CD; k0 += 32) {
        const float* pa = X + (long long)(rows + lrow) * CD + k0 + lk;
        const float* pb = X + (long long)(cols + lrow) * CD + k0 + lk;
        float4 va0 = *reinterpret_cast<const float4*>(pa);
        float4 va1 = *reinterpret_cast<const float4*>(pa + 4);
        float4 va2 = *reinterpret_cast<const float4*>(pa + 8);
        float4 va3 = *reinterpret_cast<const float4*>(pa + 12);
        float4 vb0 = *reinterpret_cast<const float4*>(pb);
        float4 vb1 = *reinterpret_cast<const float4*>(pb + 4);
        float4 vb2 = *reinterpret_cast<const float4*>(pb + 8);
        float4 vb3 = *reinterpret_cast<const float4*>(pb + 12);
        __syncthreads();
        AS(lk + 0, lrow) = va0.x;  AS(lk + 1, lrow) = va0.y;
        AS(lk + 2, lrow) = va0.z;  AS(lk + 3, lrow) = va0.w;
        AS(lk + 4, lrow) = va1.x;  AS(lk + 5, lrow) = va1.y;
        AS(lk + 6, lrow) = va1.z;  AS(lk + 7, lrow) = va1.w;
        AS(lk + 8, lrow) = va2.x;  AS(lk + 9, lrow) = va2.y;
        AS(lk + 10, lrow) = va2.z; AS(lk + 11, lrow) = va2.w;
        AS(lk + 12, lrow) = va3.x; AS(lk + 13, lrow) = va3.y;
        AS(lk + 14, lrow) = va3.z; AS(lk + 15, lrow) = va3.w;
        BS(lk + 0, lrow) = vb0.x;  BS(lk + 1, lrow) = vb0.y;
        BS(lk + 2, lrow) = vb0.z;  BS(lk + 3, lrow) = vb0.w;
        BS(lk + 4, lrow) = vb1.x;  BS(lk + 5, lrow) = vb1.y;
        BS(lk + 6, lrow) = vb1.z;  BS(lk + 7, lrow) = vb1.w;
        BS(lk + 8, lrow) = vb2.x;  BS(lk + 9, lrow) = vb2.y;
        BS(lk + 10, lrow) = vb2.z; BS(lk + 11, lrow) = vb2.w;
        BS(lk + 12, lrow) = vb3.x; BS(lk + 13, lrow) = vb3.y;
        BS(lk + 14, lrow) = vb3.z; BS(lk + 15, lrow) = vb3.w;
        __syncthreads();

        #pragma unroll 16
        for (int kk = 0; kk < 32; kk++) {
            float4 a0 = *reinterpret_cast<float4*>(&AS(kk, ty * 4));
            float4 a1 = *reinterpret_cast<float4*>(&AS(kk, 64 + ty * 4));
            float4 b0 = *reinterpret_cast<float4*>(&BS(kk, tx * 4));
            float4 b1 = *reinterpret_cast<float4*>(&BS(kk, 64 + tx * 4));
            float am[8] = {a0.x, a0.y, a0.z, a0.w, a1.x, a1.y, a1.z, a1.w};
            float bn[8] = {b0.x, b0.y, b0.z, b0.w, b1.x, b1.y, b1.z, b1.w};
            #pragma unroll
            for (int m = 0; m < 8; m++)
                #pragma unroll
                for (int n = 0; n < 8; n++)
                    acc[m][n] = __fmaf_rn(am[m], bn[n], acc[m][n]);
        }
    }

    float sr[8], sc[8];
    #pragma unroll
    for (int m = 0; m < 8; m++)
        sr[m] = g_sq[rows + (m >> 2) * 64 + ty * 4 + (m & 3)];
    #pragma unroll
    for (int n = 0; n < 8; n++)
        sc[n] = g_sq[cols + (n >> 2) * 64 + tx * 4 + (n & 3)];

    float v[8][8];
    #pragma unroll
    for (int m = 0; m < 8; m++)
        #pragma unroll
        for (int n = 0; n < 8; n++)
            v[m][n] = __fadd_rn(__fadd_rn(sr[m], sc[n]), -2.0f * acc[m][n]);

    #pragma unroll
    for (int m = 0; m < 8; m++) {
        const int gr = rows + (m >> 2) * 64 + ty * 4 + (m & 3);
        long long base = (long long)gr * NT + cols;
        __stcs(reinterpret_cast<float4*>(g_D2 + base + tx * 4),
               make_float4(v[m][0], v[m][1], v[m][2], v[m][3]));
        __stcs(reinterpret_cast<float4*>(g_D2 + base + 64 + tx * 4),
               make_float4(v[m][4], v[m][5], v[m][6], v[m][7]));
    }

    if (!diag) {
        const int wid = tid >> 5, lane = tid & 31;
        #pragma unroll
        for (int c = 0; c < 4; c++) {
            __syncthreads();
            if ((tx >> 3) == (c & 1)) {
                const int nbase = (c >> 1) * 4;
                #pragma unroll
                for (int q = 0; q < 4; q++) {
                    const int n = nbase + q;
                    const int gcl = (tx & 7) * 4 + q;
                    *reinterpret_cast<float4*>(&pool[gcl * 132 + ty * 4]) =
                        make_float4(v[0][n], v[1][n], v[2][n], v[3][n]);
                    *reinterpret_cast<float4*>(&pool[gcl * 132 + 64 + ty * 4]) =
                        make_float4(v[4][n], v[5][n], v[6][n], v[7][n]);
                }
            }
            __syncthreads();
            #pragma unroll
            for (int q = 0; q < 4; q++) {
                const int gcl = wid * 4 + q;
                const int gc = cols + c * 32 + gcl;
                float4 val = *reinterpret_cast<float4*>(&pool[gcl * 132 + lane * 4]);
                __stcs(reinterpret_cast<float4*>(
                           g_D2 + (long long)gc * NT + rows + lane * 4), val);
            }
        }
    }
}

// ---------------- kernel 3 (pass A): 5-NN density (MLP-8 streaming) ---------------
__global__ void __launch_bounds__(256) k_knn() {
    const int i = blockIdx.x;
    const int t = threadIdx.x;
    const float4* __restrict__ row4 =
        reinterpret_cast<const float4*>(g_D2 + (long long)i * NT);

    float s0 = FLTMAX, s1 = FLTMAX, s2 = FLTMAX, s3 = FLTMAX, s4 = FLTMAX;

    #define INSERT(x)                                                        \
        if (x < s4) {                                                        \
            if (x < s3) { s4 = s3;                                           \
                if (x < s2) { s3 = s2;                                       \
                    if (x < s1) { s2 = s1;                                   \
                        if (x < s0) { s1 = s0; s0 = x; } else s1 = x;        \
                    } else s2 = x;                                           \
                } else s3 = x;                                               \
            } else s4 = x;                                                   \
        }
    #define TRY4(rr)                                                         \
        {                                                                    \
            float mn = fminf(fminf(rr.x, rr.y), fminf(rr.z, rr.w));          \
            if (mn < s4) { INSERT(rr.x) INSERT(rr.y) INSERT(rr.z) INSERT(rr.w) } \
        }

    {
        float4 r0 = __ldcs(&row4[t]);
        float4 r1 = __ldcs(&row4[t + 256]);
        float4 r2 = __ldcs(&row4[t + 512]);
        float4 r3 = __ldcs(&row4[t + 768]);
        float4 r4 = __ldcs(&row4[t + 1024]);
        float4 r5 = __ldcs(&row4[t + 1280]);
        float4 r6 = __ldcs(&row4[t + 1536]);
        float4 r7 = __ldcs(&row4[t + 1792]);
        TRY4(r0) TRY4(r1) TRY4(r2) TRY4(r3)
        TRY4(r4) TRY4(r5) TRY4(r6) TRY4(r7)
    }
    #undef TRY4
    #undef INSERT

    __shared__ float sh[256 * 5];
    sh[t * 5 + 0] = s0; sh[t * 5 + 1] = s1; sh[t * 5 + 2] = s2;
    sh[t * 5 + 3] = s3; sh[t * 5 + 4] = s4;
    __syncthreads();

    for (int stride = 128; stride >= 1; stride >>= 1) {
        if (t < stride) {
            float* A = &sh[t * 5];
            float* B = &sh[(t + stride) * 5];
            float o[5];
            int ia = 0, ib = 0;
            #pragma unroll
            for (int q = 0; q < 5; q++) {
                float av = (ia < 5) ? A[ia] : FLTMAX;
                float bv = (ib < 5) ? B[ib] : FLTMAX;
                if (av <= bv) { o[q] = av; ia++; } else { o[q] = bv; ib++; }
            }
            #pragma unroll
            for (int q = 0; q < 5; q++) A[q] = o[q];
        }
        __syncthreads();
    }

    if (t == 0) {
        float accv = 0.0f;
        #pragma unroll
        for (int q = 0; q < 5; q++) {
            float d = __fdiv_rn(__fsqrt_rn(fmaxf(sh[q], 0.0f)), SQRT_C);
            accv = __fadd_rn(accv, __fmul_rn(d, d));
        }
        float mean = __fdiv_rn(accv, 5.0f);
        float dens = (float)exp(-(double)mean);
        dens = __fadd_rn(dens, __fmul_rn(jax_noise(i), 1e-6f));
        g_density[i] = dens;
    }
}

// ---------------- kernel 4 (pass B): dist_parent + score (MLP-8 streaming) --------
__global__ void __launch_bounds__(256) k_parent() {
    const int i = blockIdx.x;
    const int t = threadIdx.x;
    const float di = g_density[i];
    const float4* __restrict__ row4 =
        reinterpret_cast<const float4*>(g_D2 + (long long)i * NT);
    const float4* __restrict__ den4 =
        reinterpret_cast<const float4*>(g_density);

    float l0 = FLTMAX, l1 = FLTMAX, l2 = FLTMAX, l3 = FLTMAX;
    #define ACC4(rr, dd)                                   \
        l0 = fminf(l0, (dd.x > di) ? rr.x : FLTMAX);       \
        l1 = fminf(l1, (dd.y > di) ? rr.y : FLTMAX);       \
        l2 = fminf(l2, (dd.z > di) ? rr.z : FLTMAX);       \
        l3 = fminf(l3, (dd.w > di) ? rr.w : FLTMAX);

    {
        float4 r0 = __ldcs(&row4[t]);
        float4 r1 = __ldcs(&row4[t + 256]);
        float4 r2 = __ldcs(&row4[t + 512]);
        float4 r3 = __ldcs(&row4[t + 768]);
        float4 r4 = __ldcs(&row4[t + 1024]);
        float4 r5 = __ldcs(&row4[t + 1280]);
        float4 r6 = __ldcs(&row4[t + 1536]);
        float4 r7 = __ldcs(&row4[t + 1792]);
        float4 d0 = den4[t];
        float4 d1 = den4[t + 256];
        float4 d2 = den4[t + 512];
        float4 d3 = den4[t + 768];
        float4 d4 = den4[t + 1024];
        float4 d5 = den4[t + 1280];
        float4 d6 = den4[t + 1536];
        float4 d7 = den4[t + 1792];
        ACC4(r0, d0) ACC4(r1, d1) ACC4(r2, d2) ACC4(r3, d3)
        ACC4(r4, d4) ACC4(r5, d5) ACC4(r6, d6) ACC4(r7, d7)
    }
    #undef ACC4
    float lmin = fminf(fminf(l0, l1), fminf(l2, l3));

    __shared__ float sm[256];
    sm[t] = lmin;
    __syncthreads();
    for (int stride = 128; stride >= 1; stride >>= 1) {
        if (t < stride) sm[t] = fminf(sm[t], sm[t + stride]);
        __syncthreads();
    }

    if (t == 0) {
        float m = sm[0];
        if (m >= FLTMAX) {
            g_score[i] = FLTMAX;
        } else {
            float dp = __fdiv_rn(__fsqrt_rn(fmaxf(m, 0.0f)), SQRT_C);
            g_score[i] = __fmul_rn(dp, di);
        }
    }
}

// ---------------- kernel 5: exact top-256 via radix-select + small sort -----------
// key = (score_bits << 32) | (NT-1-i)  — identical comparator/tie-break to the
// proven full bitonic. Fast path: 12-bit-bin select -> sort <=2048 candidates.
// Deterministic fallback: full 8192 direct-key bitonic (same dyn buffer).
__global__ void k_topk(float* __restrict__ out) {
    extern __shared__ char dyn[];                              // 64KB
    unsigned int* hist = reinterpret_cast<unsigned int*>(dyn);            // 4096
    unsigned int* suf  = reinterpret_cast<unsigned int*>(dyn + 16384);    // 4096
    unsigned long long* cand = reinterpret_cast<unsigned long long*>(dyn + 32768); // 2048
    unsigned long long* keys = reinterpret_cast<unsigned long long*>(dyn);         // 8192 (fallback)
    __shared__ unsigned int shT, shC, shA, shCnt;
    const int t = threadIdx.x;  // 1024 threads

    // 1) histogram of top-12-bits
    for (int b = t; b < 4096; b += 1024) hist[b] = 0;
    __syncthreads();
    #pragma unroll
    for (int q = 0; q < 8; q++) {
        int i = q * 1024 + t;
        unsigned int bits = __float_as_uint(g_score[i]);
        atomicAdd(&hist[bits >> 20], 1u);
    }
    __syncthreads();

    // 2) suffix scan (ping-pong, 12 steps): suf[b] = count of bins >= b
    {
        unsigned int* src = hist;
        unsigned int* dst = suf;
        for (int off = 1; off < 4096; off <<= 1) {
            for (int b = t; b < 4096; b += 1024) {
                unsigned int val = src[b];
                if (b + off < 4096) val += src[b + off];
                dst[b] = val;
            }
            __syncthreads();
            unsigned int* tmp = src; src = dst; dst = tmp;
        }
        // final result in src
        for (int b = t; b < 4096; b += 1024) {
            unsigned int s = src[b];
            unsigned int snext = (b + 1 < 4096) ? src[b + 1] : 0u;
            if (s >= NCLUS && snext < NCLUS) {
                shT = (unsigned int)b;
                shC = s;
                shA = snext;
            }
        }
        if (t == 0) shCnt = 0;
    }
    __syncthreads();
    const unsigned int T = shT, C = shC;

    if (C <= 2048) {
        // 3) gather candidates
        for (int i = t; i < 2048; i += 1024) cand[i] = 0ULL;
        __syncthreads();
        #pragma unroll
        for (int q = 0; q < 8; q++) {
            int i = q * 1024 + t;
            unsigned int bits = __float_as_uint(g_score[i]);
            if ((bits >> 20) >= T) {
                unsigned int pos = atomicAdd(&shCnt, 1u);
                cand[pos] = ((unsigned long long)bits << 32) |
                            (unsigned int)(NT - 1 - i);
            }
        }
        __syncthreads();

        // 4) bitonic sort 2048 descending (1024 threads, 1 pair each per phase)
        for (int k = 2; k <= 2048; k <<= 1) {
            for (int j = k >> 1; j > 0; j >>= 1) {
                int i = ((t / j) * (j << 1)) + (t % j);
                int ixj = i + j;
                unsigned long long A = cand[i], B = cand[ixj];
                bool desc = ((i & k) == 0);
                if (desc ? (A < B) : (A > B)) { cand[i] = B; cand[ixj] = A; }
                __syncthreads();
            }
        }
        if (t < NCLUS)
            out[t] = (float)(NT - 1 - (int)(cand[t] & 0xFFFFFFFFu));
    } else {
        // fallback: full 8192 direct-key bitonic
        __syncthreads();
        #pragma unroll
        for (int q = 0; q < 8; q++) {
            int i = q * 1024 + t;
            keys[i] = ((unsigned long long)__float_as_uint(g_score[i]) << 32) |
                      (unsigned int)(NT - 1 - i);
        }
        __syncthreads();
        for (int k = 2; k <= NT; k <<= 1) {
            for (int j = k >> 1; j > 0; j >>= 1) {
                #pragma unroll
                for (int q = 0; q < 4; q++) {
                    int gid = q * 1024 + t;
                    int i = ((gid / j) * (j << 1)) + (gid % j);
                    int ixj = i + j;
                    unsigned long long A = keys[i], B = keys[ixj];
                    bool desc = ((i & k) == 0);
                    if (desc ? (A < B) : (A > B)) { keys[i] = B; keys[ixj] = A; }
                }
                __syncthreads();
            }
        }
        if (t < NCLUS)
            out[t] = (float)(NT - 1 - (int)(keys[t] & 0xFFFFFFFFu));
    }
}

// ---------------- launch ----------------
extern "C" void kernel_launch(void* const* d_in, const int* in_sizes, int n_in,
                              void* d_out, int out_size) {
    const float* X = (const float*)d_in[0];
    float* out = (float*)d_out;

    cudaFuncSetAttribute(k_topk, cudaFuncAttributeMaxDynamicSharedMemorySize, 65536);

    k_rownorm<<<NT / 8, 256>>>(X);
    k_gemm<<<(64 * 65) / 2, 256>>>(X);
    k_knn<<<NT, 256>>>();
    k_parent<<<NT, 256>>>();
    k_topk<<<1, 1024, 65536>>>(out);
}